// round 7
// baseline (speedup 1.0000x reference)
#include <cuda_runtime.h>
#include <cuda_fp16.h>
#include <cstdint>

// Problem constants
#define B_   8
#define N_   2048
#define F0_  128
#define HID_ 64
#define OUT_ 16
#define K_   10

// ---------------- device scratch (static; no allocation) ----------------
__device__ __half2 g_Lh[N_ * N_ / 2];     // 8 MB fp16 copy of L (row-major, w pairs)
__device__ float g_z[2][N_];              // ping-pong (I-L^T)^k 1 chain
__device__ float g_r[2][N_];              // ping-pong Horner accumulator
__device__ float g_a[K_ + 1];             // a_i = theta_i * C(K,i)
__device__ float g_part[B_][32][HID_];    // per-(b,chunk) partial Hg sums

__constant__ float c_binom[K_ + 1] = {1.f, 10.f, 45.f, 120.f, 210.f, 252.f,
                                      210.f, 120.f, 45.f, 10.f, 1.f};

// ---------------- convert L -> fp16, plus setup (fused) ------------------
__global__ void convert_kernel(const float* __restrict__ L,
                               const float* __restrict__ theta) {
    int idx = blockIdx.x * 256 + threadIdx.x;       // over N*N/4
    float4 f = reinterpret_cast<const float4*>(L)[idx];
    g_Lh[2 * idx]     = __floats2half2_rn(f.x, f.y);
    g_Lh[2 * idx + 1] = __floats2half2_rn(f.z, f.w);
    if (idx < N_) {
        g_z[0][idx] = 1.0f;
        g_r[0][idx] = theta[K_];      // a_K = theta_K * C(K,K)
    }
    if (idx < K_ + 1) g_a[idx] = theta[idx] * c_binom[idx];
}

// ---------------- one complete filter pass (single kernel) ---------------
// z_out = z_in - L^T z_in ;  r_out = L^T r_in + a[coefIdx] * z_out
// grid 128 blocks x 256 threads. Block owns 16 w (8 half2 columns), reduces
// over ALL v in-block: no partial buffers, no second kernel.
__global__ __launch_bounds__(256) void pass_kernel(int pin, int coefIdx) {
    __shared__ float sz[N_];            // full z_in (8 KB)
    __shared__ float sr[N_];            // full r_in (8 KB)
    __shared__ float red[4][32][8];     // (z0,z1,r0,r1) x ty-group x col

    const int tid = threadIdx.x;
    const int tx = tid & 7;             // half2 column lane (0..7)
    const int ty = tid >> 3;            // v group (0..31)

    const float* zin = g_z[pin];
    const float* rin = g_r[pin];
    for (int i = tid; i < N_; i += 256) {
        sz[i] = zin[i];
        sr[i] = rin[i];
    }
    __syncthreads();

    const int w2 = blockIdx.x * 8 + tx;            // half2 col: w = 2*w2, 2*w2+1
    const __half2* Lp = g_Lh + w2;

    float az0 = 0.f, az1 = 0.f, ar0 = 0.f, ar1 = 0.f;
#pragma unroll 16
    for (int v = ty; v < N_; v += 32) {
        float2 f = __half22float2(Lp[v * (N_ / 2)]);
        float zc = sz[v], rc = sr[v];
        az0 += f.x * zc;  az1 += f.y * zc;
        ar0 += f.x * rc;  ar1 += f.y * rc;
    }
    red[0][ty][tx] = az0;
    red[1][ty][tx] = az1;
    red[2][ty][tx] = ar0;
    red[3][ty][tx] = ar1;
    __syncthreads();

    // 16 threads: each owns one output w, sums its 32 z-partials and
    // 32 r-partials in fixed order (deterministic), writes both outputs.
    if (tid < 16) {
        const int c = tid >> 1;         // column 0..7
        const int e = tid & 1;          // 0 = even w (lane .x), 1 = odd w
        float szsum = 0.f, srsum = 0.f;
#pragma unroll
        for (int g = 0; g < 32; ++g) {
            szsum += red[e][g][c];
            srsum += red[2 + e][g][c];
        }
        const int w = blockIdx.x * 16 + 2 * c + e;
        float znew = sz[w] - szsum;
        float rnew = srsum + g_a[coefIdx] * znew;
        g_z[pin ^ 1][w] = znew;
        g_r[pin ^ 1][w] = rnew;
    }
}

// ---------------- fused Hf = relu(X@W1+b1), weighted partial reduce -----
__global__ void hf_kernel(const float* __restrict__ X,
                          const float* __restrict__ W1,
                          const float* __restrict__ b1) {
    __shared__ float w1s[F0_ * HID_];   // 32 KB
    __shared__ float b1s[HID_];
    __shared__ float red[4][32];

    int tx = threadIdx.x;               // 0..63
    int ty = threadIdx.y;               // 0..1
    int tid = ty * 64 + tx;

    for (int i = tid; i < F0_ * HID_; i += 128) w1s[i] = W1[i];
    if (tid < HID_) b1s[tid] = b1[tid];
    __syncthreads();

    int b = blockIdx.y;
    int chunk = blockIdx.x;
    int n = chunk * 64 + tx;
    const float* xr = X + ((size_t)b * N_ + n) * F0_;
    int h0 = ty * 32;

    float acc[32];
#pragma unroll
    for (int h = 0; h < 32; ++h) acc[h] = b1s[h0 + h];

    for (int f0 = 0; f0 < F0_; f0 += 16) {
        float4 xv[4];
#pragma unroll
        for (int i = 0; i < 4; ++i)
            xv[i] = reinterpret_cast<const float4*>(xr + f0)[i];
        const float* xf = reinterpret_cast<const float*>(xv);
#pragma unroll
        for (int i = 0; i < 16; ++i) {
            float x = xf[i];
            const float4* wrow =
                reinterpret_cast<const float4*>(&w1s[(f0 + i) * HID_ + h0]);
#pragma unroll
            for (int q = 0; q < 8; ++q) {
                float4 wv = wrow[q];
                acc[q * 4 + 0] += x * wv.x;
                acc[q * 4 + 1] += x * wv.y;
                acc[q * 4 + 2] += x * wv.z;
                acc[q * 4 + 3] += x * wv.w;
            }
        }
    }

    float s = g_r[0][n] * (1.0f / (float)N_);   // v[n] / N
#pragma unroll
    for (int h = 0; h < 32; ++h) acc[h] = fmaxf(acc[h], 0.f) * s;

#pragma unroll
    for (int h = 0; h < 32; ++h) {
        float v_ = acc[h];
        v_ += __shfl_xor_sync(0xffffffffu, v_, 16);
        v_ += __shfl_xor_sync(0xffffffffu, v_, 8);
        v_ += __shfl_xor_sync(0xffffffffu, v_, 4);
        v_ += __shfl_xor_sync(0xffffffffu, v_, 2);
        v_ += __shfl_xor_sync(0xffffffffu, v_, 1);
        acc[h] = v_;
    }
    int lane = tid & 31, warp = tid >> 5;
    if (lane == 0) {
#pragma unroll
        for (int h = 0; h < 32; ++h) red[warp][h] = acc[h];
    }
    __syncthreads();
    if (tid < 64) {
        int hh = tid & 31;
        int grp = tid >> 5;
        g_part[b][chunk][grp * 32 + hh] = red[grp * 2][hh] + red[grp * 2 + 1][hh];
    }
}

// ---------------- final: reduce chunks, logits = Hg@W2 + b2 -------------
__global__ void final_kernel(const float* __restrict__ W2,
                             const float* __restrict__ b2,
                             float* __restrict__ out) {
    __shared__ float hg[B_ * HID_];
    int t = threadIdx.x;                 // 512 threads = (b,h) pairs
    int b = t >> 6, h = t & 63;
    float s = 0.f;
#pragma unroll
    for (int c = 0; c < 32; ++c) s += g_part[b][c][h];
    hg[t] = s;
    __syncthreads();
    if (t < B_ * OUT_) {
        int bb = t >> 4, o = t & 15;
        float acc = b2[o];
#pragma unroll
        for (int hh = 0; hh < HID_; ++hh)
            acc += hg[bb * HID_ + hh] * W2[hh * OUT_ + o];
        out[bb * OUT_ + o] = acc;
    }
}

// ---------------- launcher ----------------------------------------------
extern "C" void kernel_launch(void* const* d_in, const int* in_sizes, int n_in,
                              void* d_out, int out_size) {
    const float* X     = (const float*)d_in[0];
    const float* L     = (const float*)d_in[1];
    const float* W1    = (const float*)d_in[2];
    const float* b1    = (const float*)d_in[3];
    const float* W2    = (const float*)d_in[4];
    const float* b2    = (const float*)d_in[5];
    const float* theta = (const float*)d_in[6];
    float* out = (float*)d_out;

    convert_kernel<<<(N_ * N_ / 4) / 256, 256>>>(L, theta);

    // 10 fused filter passes: pass j consumes parity (j-1)&1, coef a[K-j]
    for (int j = 1; j <= K_; ++j) {
        pass_kernel<<<N_ / 16, 256>>>((j - 1) & 1, K_ - j);
    }
    // final r lands in parity 0

    hf_kernel<<<dim3(32, B_), dim3(64, 2)>>>(X, W1, b1);
    final_kernel<<<1, 512>>>(W2, b2, out);
}

// round 8
// speedup vs baseline: 1.6483x; 1.6483x over previous
#include <cuda_runtime.h>
#include <cuda_fp16.h>
#include <cstdint>

// Problem constants
#define B_   8
#define N_   2048
#define F0_  128
#define HID_ 64
#define OUT_ 16
#define K_   10

#define VCHUNKS 32                   // 64 rows per chunk
#define RPC     64                   // rows per chunk

// ---------------- device scratch (static; no allocation) ----------------
__device__ __half2 g_Lh[N_ * N_ / 2];        // 8 MB fp16 L (row-major, w pairs)
__device__ float g_zvec[2][N_];              // z_{j} ping-pong (written during pass j+1)
__device__ float g_a[K_ + 1];                // a_i = theta_i * C(K,i)
__device__ float g_pz[2][VCHUNKS][N_];       // double-buffered partials of L^T z
__device__ float g_pr[2][VCHUNKS][N_];       // double-buffered partials of L^T r
__device__ float g_part[B_][32][HID_];       // per-(b,chunk) partial Hg sums

__constant__ float c_binom[K_ + 1] = {1.f, 10.f, 45.f, 120.f, 210.f, 252.f,
                                      210.f, 120.f, 45.f, 10.f, 1.f};

// ---------------- convert L -> fp16, plus coefficient setup --------------
__global__ void convert_kernel(const float* __restrict__ L,
                               const float* __restrict__ theta) {
    int idx = blockIdx.x * 256 + threadIdx.x;       // over N*N/4
    float4 f = reinterpret_cast<const float4*>(L)[idx];
    g_Lh[2 * idx]     = __floats2half2_rn(f.x, f.y);
    g_Lh[2 * idx + 1] = __floats2half2_rn(f.z, f.w);
    if (idx < K_ + 1) g_a[idx] = theta[idx] * c_binom[idx];
}

// ---------------- filter pass j (1..K): recon + partial dots -------------
// Reconstructs z_{j-1}, r_{j-1} for this block's 64-row chunk from pass
// (j-1)'s partials, then computes partials of L^T z_{j-1} / L^T r_{j-1}.
//   z_{j-1}[v] = z_{j-2}[v] - sum_c pz_{j-1}[c][v]
//   r_{j-1}[v] = sum_c pr_{j-1}[c][v] + a[K-(j-1)] * z_{j-1}[v]
// grid (8 wtiles, 32 vchunks), 128 threads. wtile-0 blocks persist z_{j-1}.
__global__ __launch_bounds__(128) void pass_kernel(int passIdx) {
    __shared__ float sz[RPC];
    __shared__ float sr[RPC];

    const int tx = threadIdx.x;        // 0..127
    const int half = tx >> 6;          // 0: z-recon, 1: r-recon
    const int t = tx & 63;
    const int v0 = blockIdx.y * RPC;
    const int v = v0 + t;
    const int pout = passIdx & 1;
    const int pin  = pout ^ 1;

    if (passIdx == 1) {
        if (half == 0) sz[t] = 1.0f;            // z_0 = 1
        else           sr[t] = g_a[K_];          // r_0 = a_K * 1
    } else if (half == 0) {
        float s = 0.f;
#pragma unroll
        for (int c = 0; c < VCHUNKS; ++c) s += g_pz[pin][c][v];
        float zold = (passIdx == 2) ? 1.0f : g_zvec[pin][v];
        float znew = zold - s;
        sz[t] = znew;
        if (blockIdx.x == 0) g_zvec[pout][v] = znew;   // persist z_{j-1}
    } else {
        float s = 0.f, sp = 0.f;
#pragma unroll
        for (int c = 0; c < VCHUNKS; ++c) {
            s  += g_pz[pin][c][v];
            sp += g_pr[pin][c][v];
        }
        float zold = (passIdx == 2) ? 1.0f : g_zvec[pin][v];
        float znew = zold - s;
        sr[t] = sp + g_a[K_ - passIdx + 1] * znew;
    }
    __syncthreads();

    // partial dots: thread owns one half2 column (2 w), 64 rows fully unrolled
    const int w2 = blockIdx.x * 128 + tx;
    const __half2* Lp = g_Lh + (size_t)v0 * (N_ / 2) + w2;

    float az0 = 0.f, az1 = 0.f, ar0 = 0.f, ar1 = 0.f;
#pragma unroll
    for (int vv = 0; vv < RPC; ++vv) {
        float2 f = __half22float2(Lp[(size_t)vv * (N_ / 2)]);
        float zc = sz[vv], rc = sr[vv];
        az0 += f.x * zc;  az1 += f.y * zc;
        ar0 += f.x * rc;  ar1 += f.y * rc;
    }
    const int c = blockIdx.y;
    reinterpret_cast<float2*>(g_pz[pout][c])[w2] = make_float2(az0, az1);
    reinterpret_cast<float2*>(g_pr[pout][c])[w2] = make_float2(ar0, ar1);
}

// ---------------- fused: reconstruct v, Hf = relu(X@W1+b1), reduce -------
// v[n] = r_K[n] = sum_c pr_K[c][n] + a[0] * (z_{K-1}[n] - sum_c pz_K[c][n])
// (pass K=10 wrote parity 0; z_9 is in g_zvec[0])
__global__ void hf_kernel(const float* __restrict__ X,
                          const float* __restrict__ W1,
                          const float* __restrict__ b1) {
    __shared__ float w1s[F0_ * HID_];   // 32 KB
    __shared__ float b1s[HID_];
    __shared__ float vsh[RPC];
    __shared__ float red[4][32];

    int tx = threadIdx.x;               // 0..63
    int ty = threadIdx.y;               // 0..1
    int tid = ty * 64 + tx;

    int chunk = blockIdx.x;
    if (ty == 0) {                       // reconstruct v for this 64-row chunk
        int n = chunk * 64 + tx;
        float s = 0.f, sp = 0.f;
#pragma unroll
        for (int c = 0; c < VCHUNKS; ++c) {
            s  += g_pz[0][c][n];
            sp += g_pr[0][c][n];
        }
        float znew = g_zvec[0][n] - s;
        vsh[tx] = sp + g_a[0] * znew;
    }

    for (int i = tid; i < F0_ * HID_; i += 128) w1s[i] = W1[i];
    if (tid < HID_) b1s[tid] = b1[tid];
    __syncthreads();

    int b = blockIdx.y;
    int n = chunk * 64 + tx;
    const float* xr = X + ((size_t)b * N_ + n) * F0_;
    int h0 = ty * 32;

    float acc[32];
#pragma unroll
    for (int h = 0; h < 32; ++h) acc[h] = b1s[h0 + h];

    for (int f0 = 0; f0 < F0_; f0 += 16) {
        float4 xv[4];
#pragma unroll
        for (int i = 0; i < 4; ++i)
            xv[i] = reinterpret_cast<const float4*>(xr + f0)[i];
        const float* xf = reinterpret_cast<const float*>(xv);
#pragma unroll
        for (int i = 0; i < 16; ++i) {
            float x = xf[i];
            const float4* wrow =
                reinterpret_cast<const float4*>(&w1s[(f0 + i) * HID_ + h0]);
#pragma unroll
            for (int q = 0; q < 8; ++q) {
                float4 wv = wrow[q];
                acc[q * 4 + 0] += x * wv.x;
                acc[q * 4 + 1] += x * wv.y;
                acc[q * 4 + 2] += x * wv.z;
                acc[q * 4 + 3] += x * wv.w;
            }
        }
    }

    float s = vsh[tx] * (1.0f / (float)N_);   // v[n] / N
#pragma unroll
    for (int h = 0; h < 32; ++h) acc[h] = fmaxf(acc[h], 0.f) * s;

#pragma unroll
    for (int h = 0; h < 32; ++h) {
        float v_ = acc[h];
        v_ += __shfl_xor_sync(0xffffffffu, v_, 16);
        v_ += __shfl_xor_sync(0xffffffffu, v_, 8);
        v_ += __shfl_xor_sync(0xffffffffu, v_, 4);
        v_ += __shfl_xor_sync(0xffffffffu, v_, 2);
        v_ += __shfl_xor_sync(0xffffffffu, v_, 1);
        acc[h] = v_;
    }
    int lane = tid & 31, warp = tid >> 5;
    if (lane == 0) {
#pragma unroll
        for (int h = 0; h < 32; ++h) red[warp][h] = acc[h];
    }
    __syncthreads();
    if (tid < 64) {
        int hh = tid & 31;
        int grp = tid >> 5;
        g_part[b][chunk][grp * 32 + hh] = red[grp * 2][hh] + red[grp * 2 + 1][hh];
    }
}

// ---------------- final: reduce chunks, logits = Hg@W2 + b2 -------------
__global__ void final_kernel(const float* __restrict__ W2,
                             const float* __restrict__ b2,
                             float* __restrict__ out) {
    __shared__ float hg[B_ * HID_];
    int t = threadIdx.x;                 // 512 threads = (b,h) pairs
    int b = t >> 6, h = t & 63;
    float s = 0.f;
#pragma unroll
    for (int c = 0; c < 32; ++c) s += g_part[b][c][h];
    hg[t] = s;
    __syncthreads();
    if (t < B_ * OUT_) {
        int bb = t >> 4, o = t & 15;
        float acc = b2[o];
#pragma unroll
        for (int hh = 0; hh < HID_; ++hh)
            acc += hg[bb * HID_ + hh] * W2[hh * OUT_ + o];
        out[bb * OUT_ + o] = acc;
    }
}

// ---------------- launcher ----------------------------------------------
extern "C" void kernel_launch(void* const* d_in, const int* in_sizes, int n_in,
                              void* d_out, int out_size) {
    const float* X     = (const float*)d_in[0];
    const float* L     = (const float*)d_in[1];
    const float* W1    = (const float*)d_in[2];
    const float* b1    = (const float*)d_in[3];
    const float* W2    = (const float*)d_in[4];
    const float* b2    = (const float*)d_in[5];
    const float* theta = (const float*)d_in[6];
    float* out = (float*)d_out;

    convert_kernel<<<(N_ * N_ / 4) / 256, 256>>>(L, theta);

    for (int j = 1; j <= K_; ++j) {
        pass_kernel<<<dim3(8, VCHUNKS), 128>>>(j);
    }

    hf_kernel<<<dim3(32, B_), dim3(64, 2)>>>(X, W1, b1);
    final_kernel<<<1, 512>>>(W2, b2, out);
}

// round 9
// speedup vs baseline: 1.8776x; 1.1391x over previous
#include <cuda_runtime.h>
#include <cuda_fp16.h>
#include <cstdint>

// Problem constants
#define B_   8
#define N_   2048
#define F0_  128
#define HID_ 64
#define OUT_ 16
#define K_   10

#define VCHUNKS 32                  // 64 rows per chunk
#define RPC     64                  // rows per chunk
#define GRID    256                 // 8 wtiles x 32 vchunks
#define TPB     128

// ---------------- device scratch (static; no allocation) ----------------
__device__ float g_zvec[2][N_];              // persisted z_{j-1} ping-pong
__device__ float g_pz[2][VCHUNKS][N_];       // double-buffered partials of L^T z
__device__ float g_pr[2][VCHUNKS][N_];       // double-buffered partials of L^T r
__device__ float g_part[B_][32][HID_];       // per-(b,chunk) partial Hg sums
__device__ unsigned g_barcnt = 0;            // monotonic ticket counter
__device__ unsigned g_barrel = 0;            // monotonic release generation

__constant__ float c_binom[K_ + 1] = {1.f, 10.f, 45.f, 120.f, 210.f, 252.f,
                                      210.f, 120.f, 45.f, 10.f, 1.f};

// Grid barrier: monotonic counters stay consistent across graph replays.
__device__ __forceinline__ void grid_arrive_wait() {
    __threadfence();
    unsigned ticket = atomicAdd(&g_barcnt, 1u) + 1u;
    unsigned gen = (ticket + GRID - 1u) / GRID;
    if ((ticket & (GRID - 1u)) == 0u) {
        atomicAdd(&g_barrel, 1u);
    }
    int spins = 0;
    while (*((volatile unsigned*)&g_barrel) < gen) {
        if (++spins > 64) __nanosleep(32);
    }
    __threadfence();
}

__device__ __forceinline__ void gsync(int tid) {
    __syncthreads();
    if (tid == 0) grid_arrive_wait();
    __syncthreads();
}

__global__ __launch_bounds__(TPB) void mega_kernel(
    const float* __restrict__ X,  const float* __restrict__ L,
    const float* __restrict__ W1, const float* __restrict__ b1,
    const float* __restrict__ W2, const float* __restrict__ b2,
    const float* __restrict__ theta, float* __restrict__ out)
{
    extern __shared__ char dynsmem[];            // 32 KB: L-tile, later W1
    __half2* tile = reinterpret_cast<__half2*>(dynsmem);   // [64][128]
    float*   w1s  = reinterpret_cast<float*>(dynsmem);     // hf-phase alias

    __shared__ float sz[RPC], sr[RPC];
    __shared__ float b1s[HID_];
    __shared__ float vsh[RPC];
    __shared__ float red[4][32];
    __shared__ float hg[B_ * HID_];

    const int tid = threadIdx.x;
    const int bid = blockIdx.x;
    const int wtile = bid & 7;
    const int vchunk = bid >> 3;
    const int v0 = vchunk * RPC;

    // ---- Phase 0: convert MY 64x256 fp32 L tile into smem fp16 ----------
    {
        const float* Lsrc = L + (size_t)v0 * N_ + wtile * 256;
        for (int i = tid; i < 64 * 64; i += TPB) {     // 64 rows x 64 float4
            int row = i >> 6, q = i & 63;
            float4 f = reinterpret_cast<const float4*>(Lsrc + (size_t)row * N_)[q];
            tile[row * 128 + 2 * q]     = __floats2half2_rn(f.x, f.y);
            tile[row * 128 + 2 * q + 1] = __floats2half2_rn(f.z, f.w);
        }
    }
    __syncthreads();

    // ---- Passes 1..K: recon z/r for my chunk, partial dots from smem ----
    const int half = tid >> 6;          // 0: z-recon, 1: r-recon
    const int t = tid & 63;
    const int v = v0 + t;

    for (int j = 1; j <= K_; ++j) {
        const int pout = j & 1;
        const int pin  = pout ^ 1;

        if (j > 1) gsync(tid);          // partials of pass j-1 complete

        if (j == 1) {
            if (half == 0) sz[t] = 1.0f;                       // z_0
            else           sr[t] = theta[K_];                  // r_0 = a_K
        } else if (half == 0) {
            float s = 0.f;
#pragma unroll
            for (int c = 0; c < VCHUNKS; ++c) s += g_pz[pin][c][v];
            float zold = (j == 2) ? 1.0f : g_zvec[pin][v];
            float znew = zold - s;
            sz[t] = znew;
            if (wtile == 0) g_zvec[pout][v] = znew;            // persist z_{j-1}
        } else {
            float s = 0.f, sp = 0.f;
#pragma unroll
            for (int c = 0; c < VCHUNKS; ++c) {
                s  += g_pz[pin][c][v];
                sp += g_pr[pin][c][v];
            }
            float zold = (j == 2) ? 1.0f : g_zvec[pin][v];
            float znew = zold - s;
            float aj = theta[K_ - j + 1] * c_binom[K_ - j + 1];
            sr[t] = sp + aj * znew;
        }
        __syncthreads();

        float az0 = 0.f, az1 = 0.f, ar0 = 0.f, ar1 = 0.f;
#pragma unroll
        for (int vv = 0; vv < RPC; ++vv) {
            float2 f = __half22float2(tile[vv * 128 + tid]);
            float zc = sz[vv], rc = sr[vv];
            az0 += f.x * zc;  az1 += f.y * zc;
            ar0 += f.x * rc;  ar1 += f.y * rc;
        }
        const int w2 = wtile * 128 + tid;
        reinterpret_cast<float2*>(g_pz[pout][vchunk])[w2] = make_float2(az0, az1);
        reinterpret_cast<float2*>(g_pr[pout][vchunk])[w2] = make_float2(ar0, ar1);
        __syncthreads();
    }

    gsync(tid);                          // pass-K partials complete (parity 0)

    // ---- hf phase: remap blocks, reconstruct v, GEMM + weighted reduce --
    {
        const int chunk = bid & 31;
        const int b = bid >> 5;
        const int tx = tid & 63;
        const int ty = tid >> 6;

        if (ty == 0) {                   // v[n] for my 64-row chunk
            int n = chunk * 64 + tx;
            float s = 0.f, sp = 0.f;
#pragma unroll
            for (int c = 0; c < VCHUNKS; ++c) {
                s  += g_pz[0][c][n];
                sp += g_pr[0][c][n];
            }
            float znew = g_zvec[0][n] - s;
            vsh[tx] = sp + theta[0] * znew;       // a_0 = theta_0 * 1
        }
        __syncthreads();                 // tile dead -> safe to overwrite

        for (int i = tid; i < F0_ * HID_; i += TPB) w1s[i] = W1[i];
        if (tid < HID_) b1s[tid] = b1[tid];
        __syncthreads();

        const int n = chunk * 64 + tx;
        const float* xr = X + ((size_t)b * N_ + n) * F0_;
        const int h0 = ty * 32;

        float acc[32];
#pragma unroll
        for (int h = 0; h < 32; ++h) acc[h] = b1s[h0 + h];

        for (int f0 = 0; f0 < F0_; f0 += 16) {
            float4 xv[4];
#pragma unroll
            for (int i = 0; i < 4; ++i)
                xv[i] = reinterpret_cast<const float4*>(xr + f0)[i];
            const float* xf = reinterpret_cast<const float*>(xv);
#pragma unroll
            for (int i = 0; i < 16; ++i) {
                float x = xf[i];
                const float4* wrow =
                    reinterpret_cast<const float4*>(&w1s[(f0 + i) * HID_ + h0]);
#pragma unroll
                for (int q = 0; q < 8; ++q) {
                    float4 wv = wrow[q];
                    acc[q * 4 + 0] += x * wv.x;
                    acc[q * 4 + 1] += x * wv.y;
                    acc[q * 4 + 2] += x * wv.z;
                    acc[q * 4 + 3] += x * wv.w;
                }
            }
        }

        float s = vsh[tx] * (1.0f / (float)N_);
#pragma unroll
        for (int h = 0; h < 32; ++h) acc[h] = fmaxf(acc[h], 0.f) * s;

#pragma unroll
        for (int h = 0; h < 32; ++h) {
            float v_ = acc[h];
            v_ += __shfl_xor_sync(0xffffffffu, v_, 16);
            v_ += __shfl_xor_sync(0xffffffffu, v_, 8);
            v_ += __shfl_xor_sync(0xffffffffu, v_, 4);
            v_ += __shfl_xor_sync(0xffffffffu, v_, 2);
            v_ += __shfl_xor_sync(0xffffffffu, v_, 1);
            acc[h] = v_;
        }
        int lane = tid & 31, warp = tid >> 5;
        if (lane == 0) {
#pragma unroll
            for (int h = 0; h < 32; ++h) red[warp][h] = acc[h];
        }
        __syncthreads();
        if (tid < 64) {
            int hh = tid & 31;
            int grp = tid >> 5;
            g_part[b][chunk][grp * 32 + hh] = red[grp * 2][hh] + red[grp * 2 + 1][hh];
        }
    }

    gsync(tid);                          // all g_part written

    // ---- final: block 0 reduces chunks, logits = Hg@W2 + b2 ------------
    if (bid == 0) {
        for (int i = tid; i < B_ * HID_; i += TPB) {
            int bb = i >> 6, hh = i & 63;
            float s = 0.f;
#pragma unroll
            for (int c = 0; c < 32; ++c) s += g_part[bb][c][hh];
            hg[i] = s;
        }
        __syncthreads();
        {   // 128 threads = 8 batches x 16 outputs
            int bb = tid >> 4, o = tid & 15;
            float acc = b2[o];
#pragma unroll
            for (int hh = 0; hh < HID_; ++hh)
                acc += hg[bb * HID_ + hh] * W2[hh * OUT_ + o];
            out[bb * OUT_ + o] = acc;
        }
    }
}

// ---------------- launcher ----------------------------------------------
extern "C" void kernel_launch(void* const* d_in, const int* in_sizes, int n_in,
                              void* d_out, int out_size) {
    const float* X     = (const float*)d_in[0];
    const float* L     = (const float*)d_in[1];
    const float* W1    = (const float*)d_in[2];
    const float* b1    = (const float*)d_in[3];
    const float* W2    = (const float*)d_in[4];
    const float* b2    = (const float*)d_in[5];
    const float* theta = (const float*)d_in[6];
    float* out = (float*)d_out;

    mega_kernel<<<GRID, TPB, 32 * 1024>>>(X, L, W1, b1, W2, b2, theta, out);
}